// round 17
// baseline (speedup 1.0000x reference)
#include <cuda_runtime.h>
#include <cuda_fp16.h>
#include <cstdint>

// ============================================================================
// out[B, OUT] = x[B, IN] @ W[OUT, IN]^T + b[OUT], fp32, 4096^3.
// Plain sm_103 target -> fp16 HMMA single pass (products exact in fp32).
// R17: 3 CTAs/SM decorrelation + finer tiles. BM=128 BN=64 BK=64, 3 stages
//      x 24KB = 72KB, launch_bounds(128,3). Tile count 2048 -> 5 waves
//      (tail 86.5% -> 92.2%); 3 independent CTA phases per SM.
//      (R12 geometry with the 2-stage/wait-0 defects repaired.)
// ============================================================================

#define DIM 4096

__device__ __half g_xh[(size_t)DIM * DIM];
__device__ __half g_wh[(size_t)DIM * DIM];

// ----------------------------------------------------------------------------
// helpers
// ----------------------------------------------------------------------------
__device__ __forceinline__ uint32_t smem_u32(const void* p) {
    uint32_t a;
    asm("{ .reg .u64 t; cvta.to.shared.u64 t, %1; cvt.u32.u64 %0, t; }"
        : "=r"(a) : "l"(p));
    return a;
}

__device__ __forceinline__ void cp16(uint32_t dst, const void* src) {
    asm volatile("cp.async.cg.shared.global [%0], [%1], 16;"
                 :: "r"(dst), "l"(src));
}
#define CP_COMMIT() asm volatile("cp.async.commit_group;" ::: "memory")
#define CP_WAIT()   asm volatile("cp.async.wait_group 1;"  ::: "memory")

__device__ __forceinline__ void ldm4(uint32_t* r, uint32_t addr) {
    asm volatile("ldmatrix.sync.aligned.m8n8.x4.shared.b16 {%0,%1,%2,%3}, [%4];"
                 : "=r"(r[0]), "=r"(r[1]), "=r"(r[2]), "=r"(r[3]) : "r"(addr));
}

__device__ __forceinline__ void mma16816(float* d, const uint32_t* a, const uint32_t* b) {
    asm volatile(
        "mma.sync.aligned.m16n8k16.row.col.f32.f16.f16.f32 "
        "{%0,%1,%2,%3}, {%4,%5,%6,%7}, {%8,%9}, {%0,%1,%2,%3};"
        : "+f"(d[0]), "+f"(d[1]), "+f"(d[2]), "+f"(d[3])
        : "r"(a[0]), "r"(a[1]), "r"(a[2]), "r"(a[3]), "r"(b[0]), "r"(b[1]));
}

// ----------------------------------------------------------------------------
// Kernel 1: fp32 -> fp16 (R16 version: MLP-4 loads, 16B coalesced stores)
// ----------------------------------------------------------------------------
__device__ __forceinline__ uint32_t pack2(float a, float b) {
    __half2 h = __floats2half2_rn(a, b);
    return *(const uint32_t*)&h;
}

__global__ void __launch_bounds__(256)
convert_half(const float* __restrict__ x, const float* __restrict__ W) {
    const bool isw = blockIdx.x >= 4096;
    const float4* __restrict__ src = (const float4*)(isw ? W : x);
    uint4* __restrict__ dst = (uint4*)(isw ? g_wh : g_xh);
    const int blk = isw ? blockIdx.x - 4096 : blockIdx.x;
    const int j0 = blk * 1024 + threadIdx.x * 2;
    const int d0 = blk * 512 + threadIdx.x;

    float4 f0 = __ldcs(src + j0);
    float4 f1 = __ldcs(src + j0 + 1);
    float4 f2 = __ldcs(src + j0 + 512);
    float4 f3 = __ldcs(src + j0 + 513);

    uint4 o0, o1;
    o0.x = pack2(f0.x, f0.y); o0.y = pack2(f0.z, f0.w);
    o0.z = pack2(f1.x, f1.y); o0.w = pack2(f1.z, f1.w);
    o1.x = pack2(f2.x, f2.y); o1.y = pack2(f2.z, f2.w);
    o1.z = pack2(f3.x, f3.y); o1.w = pack2(f3.z, f3.w);

    __stcs(dst + d0, o0);
    __stcs(dst + d0 + 256, o1);
}

// ----------------------------------------------------------------------------
// Kernel 2: fp16 HMMA GEMM. BM=128 BN=64 BK=64, 3 stages, 4 warps (2x2,
// warp tile 64x32), 3 CTAs/SM. 128B rows, 8-way SW128 swizzle.
// ----------------------------------------------------------------------------
static constexpr int BM = 128;
static constexpr int BN = 64;
static constexpr int BK = 64;                    // fp16 elems (128B rows)
static constexpr int NK = DIM / BK;              // 64 iterations
static constexpr int NTHREADS = 128;

static constexpr int A_B = BM * BK * 2;          // 16384
static constexpr int B_B = BN * BK * 2;          // 8192
static constexpr int OFF_A = 0;
static constexpr int OFF_B = A_B;
static constexpr int STAGE_B = A_B + B_B;        // 24576
static constexpr int STAGES = 3;
static constexpr int SMEM_BYTES = STAGES * STAGE_B;  // 73728 -> 3 CTAs/SM

// SW128 swizzle: row r (128B rows), 16B unit u in [0,8)
__device__ __forceinline__ uint32_t sw_off(int r, int u) {
    return (uint32_t)(r * 128 + ((u ^ (r & 7)) << 4));
}

// A: 128 rows -> 8 cp16/thread; B: 64 rows -> 4 cp16/thread
__device__ __forceinline__ void load_stage(uint32_t st, int tm, int bn0, int k0, int tid) {
#pragma unroll
    for (int i = 0; i < 8; i++) {
        int c = tid + i * NTHREADS;
        int r = c >> 3, u = c & 7;
        cp16(st + OFF_A + sw_off(r, u),
             g_xh + (size_t)(tm * BM + r) * DIM + k0 + u * 8);
    }
#pragma unroll
    for (int i = 0; i < 4; i++) {
        int c = tid + i * NTHREADS;
        int r = c >> 3, u = c & 7;
        cp16(st + OFF_B + sw_off(r, u),
             g_wh + (size_t)(bn0 + r) * DIM + k0 + u * 8);
    }
}

__global__ void __launch_bounds__(NTHREADS, 3)
gemm_kernel(const float* __restrict__ bias, float* __restrict__ out) {
    extern __shared__ char smem[];
    const uint32_t sb = smem_u32(smem);
    const int tid = threadIdx.x;
    const int wid = tid >> 5;
    const int lane = tid & 31;
    const int warp_m = wid & 1;      // 2 warps along M (64 rows each)
    const int warp_n = wid >> 1;     // 2 warps along N (32 cols each)

    // Grid: 32 tm x 64 tn = 2048 CTAs, tn-major.
    const int bid = blockIdx.x;
    const int tm = bid & 31;
    const int bn0 = (bid >> 5) * BN;

    // ldmatrix lane addressing, 128B rows (proven fragment maps:
    // A from R13 core, B from R15 tail kernel).
    const int a_idx = lane >> 3;
    const int a_row = warp_m * 64 + (lane & 7) + (a_idx & 1) * 8;
    const int a_kk  = a_idx >> 1;
    const int b_idx = lane >> 3;
    const int b_row = warp_n * 32 + (lane & 7) + (b_idx >> 1) * 8;
    const int b_kk  = b_idx & 1;
    const int lsw   = lane & 7;

    uint32_t ua[4], ub[4];
#pragma unroll
    for (int ks = 0; ks < 4; ks++) {
        ua[ks] = (uint32_t)(((ks * 2 + a_kk) ^ lsw) << 4);
        ub[ks] = (uint32_t)(((ks * 2 + b_kk) ^ lsw) << 4);
    }
    const uint32_t a_base = (uint32_t)(a_row * 128);   // + mt*2048
    const uint32_t b_base = (uint32_t)(b_row * 128);   // + p*2048

    float acc[4][4][4];
#pragma unroll
    for (int mt = 0; mt < 4; mt++)
#pragma unroll
        for (int nt = 0; nt < 4; nt++)
#pragma unroll
            for (int j = 0; j < 4; j++) acc[mt][nt][j] = 0.f;

    // Prologue: fill STAGES-1 = 2 stages
#pragma unroll
    for (int s = 0; s < STAGES - 1; s++) {
        load_stage(sb + s * STAGE_B, tm, bn0, s * BK, tid);
        CP_COMMIT();
    }

    int s_cur = 0;                  // stage of iteration kt
    int s_nxt = STAGES - 1;         // stage receiving kt + STAGES-1
    for (int kt = 0; kt < NK; kt++) {
        CP_WAIT();
        __syncthreads();

        // Issue next-stage loads first (that stage was last read at kt-1;
        // the barrier above makes the overwrite safe).
        const int kn = kt + STAGES - 1;
        if (kn < NK)
            load_stage(sb + s_nxt * STAGE_B, tm, bn0, kn * BK, tid);
        CP_COMMIT();   // unconditional: keeps wait_group accounting exact

        const uint32_t stg = sb + s_cur * STAGE_B;
#pragma unroll
        for (int ks = 0; ks < 4; ks++) {
            uint32_t a[4][4];
#pragma unroll
            for (int mt = 0; mt < 4; mt++)
                ldm4(a[mt], stg + OFF_A + a_base + mt * 2048 + ua[ks]);
            uint32_t b[2][4];
#pragma unroll
            for (int p = 0; p < 2; p++)
                ldm4(b[p], stg + OFF_B + b_base + p * 2048 + ub[ks]);
#pragma unroll
            for (int mt = 0; mt < 4; mt++) {
#pragma unroll
                for (int nt = 0; nt < 4; nt++) {
                    const int p = nt >> 1, h = (nt & 1) * 2;
                    mma16816(acc[mt][nt], a[mt], &b[p][h]);
                }
            }
        }

        if (++s_cur == STAGES) s_cur = 0;
        if (++s_nxt == STAGES) s_nxt = 0;
    }

    // Epilogue: add bias, store fp32
    const int m0 = tm * BM + warp_m * 64;
    const int n0 = bn0 + warp_n * 32;
    const int er = lane >> 2;
    const int ec = (lane & 3) * 2;
#pragma unroll
    for (int nt = 0; nt < 4; nt++) {
        const int col = n0 + nt * 8 + ec;
        const float b0 = __ldg(bias + col);
        const float b1 = __ldg(bias + col + 1);
#pragma unroll
        for (int mt = 0; mt < 4; mt++) {
            const int row = m0 + mt * 16 + er;
            float2 v0 = make_float2(acc[mt][nt][0] + b0, acc[mt][nt][1] + b1);
            float2 v1 = make_float2(acc[mt][nt][2] + b0, acc[mt][nt][3] + b1);
            *(float2*)(out + (size_t)row * DIM + col) = v0;
            *(float2*)(out + (size_t)(row + 8) * DIM + col) = v1;
        }
    }
}

// ----------------------------------------------------------------------------
// kernel_launch
// ----------------------------------------------------------------------------
extern "C" void kernel_launch(void* const* d_in, const int* in_sizes, int n_in,
                              void* d_out, int out_size) {
    const float* x = (const float*)d_in[0];
    const float* W = (const float*)d_in[1];
    const float* b = (const float*)d_in[2];
    float* out = (float*)d_out;

    cudaFuncSetAttribute(gemm_kernel,
                         cudaFuncAttributeMaxDynamicSharedMemorySize, SMEM_BYTES);

    convert_half<<<8192, 256>>>(x, W);

    const int grid = (DIM / BM) * (DIM / BN);   // 32 * 64 = 2048
    gemm_kernel<<<grid, NTHREADS, SMEM_BYTES>>>(b, out);
}